// round 16
// baseline (speedup 1.0000x reference)
#include <cuda_runtime.h>
#include <cstdint>

#define B_   8
#define N_   64
#define NUM_CLASSES 81
#define C_   86
#define NLEV 5
#define NROWS 248
#define UNITS8_PER_B 43648
#define TOTAL_UNITS (B_ * UNITS8_PER_B)       // 349184
#define WBLK 128
#define WGRID 1480

typedef unsigned long long u64;

__constant__ int   c_H[NLEV]      = {128, 64, 32, 16, 8};
__constant__ float c_ps[NLEV]     = {0.0078125f, 0.015625f, 0.03125f, 0.0625f, 0.125f};
__constant__ float c_invps[NLEV]  = {128.0f, 64.0f, 32.0f, 16.0f, 8.0f};
__constant__ float c_th0[NLEV]    = {0.0078125f, 0.0625f, 0.125f, 0.25f, 0.5f};
__constant__ float c_th1[NLEV]    = {0.0625f, 0.125f, 0.25f, 0.5f, 1.0f};

// scratch (no allocation allowed)
__device__ float4 g_sboxes[B_][N_];
__device__ int    g_slabels[B_][N_];
__device__ u64    g_cov[B_][NLEV][128][2];
__device__ u64    g_cand[B_][NLEV][128];

// ---------------- K1: fused sort + per-row masks (validated R8-R13) ----------------
__global__ __launch_bounds__(256)
void prep_kernel(const float* __restrict__ boxes,
                 const int* __restrict__ labels) {
    const int b   = blockIdx.y;
    const int tid = threadIdx.x;
    __shared__ float  s_area[N_];
    __shared__ float4 s_sb[N_];
    __shared__ int    s_sl[N_];

    float4 w0;
    int lab0 = 0;
    if (tid < N_) {
        const float* bx = boxes + ((size_t)b * N_ + tid) * 4;
        w0 = make_float4(bx[0], bx[1], bx[2], bx[3]);
        lab0 = labels[(size_t)b * N_ + tid];
        s_area[tid] = (w0.z - w0.x) * (w0.w - w0.y);
    }
    __syncthreads();
    if (tid < N_) {
        float a = s_area[tid];
        int rank = 0;
#pragma unroll
        for (int j = 0; j < N_; j++) {
            float aj = s_area[j];
            rank += (aj > a) || (aj == a && j < tid);
        }
        s_sb[rank] = w0;
        s_sl[rank] = lab0;
    }
    __syncthreads();

    if (blockIdx.x == 0 && tid < N_) {
        g_sboxes[b][tid]  = s_sb[tid];
        g_slabels[b][tid] = s_sl[tid];
    }

    const int lane = tid & 31;
    const int rid  = blockIdx.x * 8 + (tid >> 5);
    if (rid >= NROWS) return;

    int lev, y;
    if      (rid < 128) { lev = 0; y = rid; }
    else if (rid < 192) { lev = 1; y = rid - 128; }
    else if (rid < 224) { lev = 2; y = rid - 192; }
    else if (rid < 240) { lev = 3; y = rid - 224; }
    else                { lev = 4; y = rid - 240; }

    const int   H     = c_H[lev];
    const float ps    = c_ps[lev];
    const float invps = c_invps[lev];
    const float t0m   = c_th0[lev] * 0.999f;
    const float t1m   = c_th1[lev] * 1.001f;
    const float my    = ((float)y + 0.5f) * ps;

    u64 cv0 = 0ull, cv1 = 0ull, cand = 0ull;
#pragma unroll
    for (int t = 0; t < 2; t++) {
        const int n = lane + t * 32;
        float4 w = s_sb[n];
        if (my >= w.y && my <= w.w) {
            float md = fmaxf(w.z - w.x, w.w - w.y);
            if (md > t0m && 0.5f * md <= t1m) cand |= 1ull << n;

            int xlo = (int)ceilf(w.x * invps - 0.5f);
            if (((float)(xlo - 1) + 0.5f) * ps >= w.x) xlo--;
            else if (((float)xlo + 0.5f) * ps < w.x)  xlo++;
            int xhi = (int)floorf(w.z * invps - 0.5f);
            if (((float)(xhi + 1) + 0.5f) * ps <= w.z) xhi++;
            else if (((float)xhi + 0.5f) * ps > w.z)   xhi--;
            if (xlo < 0) xlo = 0;
            if (xhi > H - 1) xhi = H - 1;
            if (xlo <= xhi) {
                int l0 = xlo < 64 ? xlo : 64;
                int h0 = (xhi + 1) < 64 ? (xhi + 1) : 64;
                if (h0 > l0)
                    cv0 |= ((h0 == 64) ? ~0ull : ((1ull << h0) - 1)) & ~((1ull << l0) - 1);
                int l1 = xlo - 64 > 0 ? xlo - 64 : 0;
                int h1 = xhi + 1 - 64 > 0 ? xhi + 1 - 64 : 0;
                if (h1 > l1)
                    cv1 |= ((h1 == 64) ? ~0ull : ((1ull << h1) - 1)) & ~((1ull << l1) - 1);
            }
        }
    }
#pragma unroll
    for (int off = 16; off > 0; off >>= 1) {
        cv0  |= __shfl_xor_sync(0xFFFFFFFFu, cv0,  off);
        cv1  |= __shfl_xor_sync(0xFFFFFFFFu, cv1,  off);
        cand |= __shfl_xor_sync(0xFFFFFFFFu, cand, off);
    }
    if (lane == 0) {
        g_cov[b][lev][y][0] = cv0;
        g_cov[b][lev][y][1] = cv1;
        g_cand[b][lev][y]   = cand;
    }
}

// ---------------- level constants helper ----------------
template <int LEV> struct LC {
    static constexpr int    H    = (LEV == 0) ? 128 : (LEV == 1) ? 64 : (LEV == 2) ? 32
                                 : (LEV == 3) ? 16 : 8;
    static constexpr int    HH   = H * H;
    static constexpr int    gsh  = (LEV == 0) ? 12 : (LEV == 1) ? 10 : (LEV == 2) ? 8
                                 : (LEV == 3) ? 6 : 4;
    static constexpr int    logH = (LEV == 0) ? 7 : (LEV == 1) ? 6 : (LEV == 2) ? 5
                                 : (LEV == 3) ? 4 : 3;
    static constexpr float  ps   = 1.0f / (float)H;
    static constexpr float  th0  = (LEV == 0) ? 0.0078125f : (LEV == 1) ? 0.0625f
                                 : (LEV == 2) ? 0.125f : (LEV == 3) ? 0.25f : 0.5f;
    static constexpr float  th1  = (LEV == 0) ? 0.0625f : (LEV == 1) ? 0.125f
                                 : (LEV == 2) ? 0.25f : (LEV == 3) ? 0.5f : 1.0f;
    static constexpr size_t base = (LEV == 0) ? 0ull : (LEV == 1) ? 11272192ull
                                 : (LEV == 2) ? 14090240ull : (LEV == 3) ? 14794752ull
                                 : 14970880ull;
};

// ---------------- phase 1: zero fill (no metadata dependency) ----------------
template <int LEV>
__device__ __forceinline__ void zero_unit(float* __restrict__ out, int b, int local) {
    using L = LC<LEV>;
    constexpr size_t cs = (size_t)L::HH;
    const int s = local >> L::gsh;
    const int g = local & ((1 << L::gsh) - 1);
    const int gx4 = g << 2;
    const int y   = gx4 >> L::logH;
    const int x0  = gx4 & (L::H - 1);

    float* rowp = out + L::base + (size_t)b * (C_ * cs) + (size_t)y * L::H + x0;
    float* slicep = rowp + (size_t)(11 * s) * cs;
    const float4 z = make_float4(0.0f, 0.0f, 0.0f, 0.0f);
    if (s == 7) {
#pragma unroll
        for (int i = 0; i < 9; i++)
            *reinterpret_cast<float4*>(slicep + (size_t)i * cs) = z;
    } else {
#pragma unroll
        for (int i = 0; i < 11; i++)
            *reinterpret_cast<float4*>(slicep + (size_t)i * cs) = z;
    }
}

// ---------------- phase 2: sparse patches (after grid dependency sync) --------
template <int LEV>
__device__ __forceinline__ void patch_unit(float* __restrict__ out, int b, int local) {
    using L = LC<LEV>;
    constexpr size_t cs = (size_t)L::HH;
    const int s = local >> L::gsh;
    const int g = local & ((1 << L::gsh) - 1);
    const int gx4 = g << 2;
    const int y   = gx4 >> L::logH;
    const int x0  = gx4 & (L::H - 1);

    u64 cand = g_cand[b][LEV][y];
    const u64 cov = (s == 0) ? g_cov[b][LEV][y][x0 >> 6] : 0ull;

    float* rowp = out + L::base + (size_t)b * (C_ * cs) + (size_t)y * L::H + x0;
    float* clsp = rowp + 5 * cs;
    const int sh = x0 & 63;

    if (cand == 0ull) {
        if (s == 0) {
#pragma unroll
            for (int k = 0; k < 4; k++)
                if (!((cov >> (sh + k)) & 1ull)) clsp[k] = 1.0f;   // background
        }
        return;
    }

    const float my = ((float)y + 0.5f) * L::ps;
    float mx[4];
#pragma unroll
    for (int k = 0; k < 4; k++) mx[k] = ((float)(x0 + k) + 0.5f) * L::ps;

    int win[4] = {-1, -1, -1, -1};
    while (cand) {
        const int n = __ffsll((long long)cand) - 1;
        cand &= cand - 1;
        float4 w = g_sboxes[b][n];
        float t   = my - w.y;
        float bo  = w.w - my;
        float tbx = fmaxf(t, bo);
#pragma unroll
        for (int k = 0; k < 4; k++) {
            float l = mx[k] - w.x, rr = w.z - mx[k];
            float mxv = fmaxf(fmaxf(l, rr), tbx);
            if (fminf(l, rr) >= 0.0f && mxv > L::th0 && mxv <= L::th1) win[k] = n;
        }
    }

    if (s == 0) {
        bool anyw = (win[0] >= 0) || (win[1] >= 0) || (win[2] >= 0) || (win[3] >= 0);
        if (anyw) {
            float rl[4], rt[4], rr_[4], rb[4], ce[4];
#pragma unroll
            for (int k = 0; k < 4; k++) {
                if (win[k] >= 0) {
                    float4 w = g_sboxes[b][win[k]];
                    float l  = mx[k] - w.x;
                    float t  = my    - w.y;
                    float rr = w.z - mx[k];
                    float bo = w.w - my;
                    rl[k] = l; rt[k] = t; rr_[k] = rr; rb[k] = bo;
                    float dx = fminf(l, rr),  Dx = fmaxf(l, rr);
                    float dy = fminf(t, bo),  Dy = fmaxf(t, bo);
                    float arg = (dx / (Dx != 0.0f ? Dx : 1.0f)) *
                                (dy / (Dy != 0.0f ? Dy : 1.0f));
                    ce[k] = (arg > 0.0f) ? sqrtf(arg) : 0.0f;
                } else {
                    rl[k] = rt[k] = rr_[k] = rb[k] = 0.0f;
                    ce[k] = 0.0f;
                }
            }
            *reinterpret_cast<float4*>(rowp + 0 * cs) = make_float4(rl[0], rl[1], rl[2], rl[3]);
            *reinterpret_cast<float4*>(rowp + 1 * cs) = make_float4(rt[0], rt[1], rt[2], rt[3]);
            *reinterpret_cast<float4*>(rowp + 2 * cs) = make_float4(rr_[0], rr_[1], rr_[2], rr_[3]);
            *reinterpret_cast<float4*>(rowp + 3 * cs) = make_float4(rb[0], rb[1], rb[2], rb[3]);
            *reinterpret_cast<float4*>(rowp + 4 * cs) = make_float4(ce[0], ce[1], ce[2], ce[3]);
        }
#pragma unroll
        for (int k = 0; k < 4; k++) {
            if (win[k] >= 0) {
                int lab = g_slabels[b][win[k]];
                if (lab < 6) clsp[(size_t)lab * cs + k] = 1.0f;
            } else if (!((cov >> (sh + k)) & 1ull)) {
                clsp[k] = 1.0f;
            }
        }
    } else {
        const int lo = 11 * s - 5;
        const int hi = (s == 7) ? NUM_CLASSES : lo + 11;
#pragma unroll
        for (int k = 0; k < 4; k++) {
            if (win[k] >= 0) {
                int lab = g_slabels[b][win[k]];
                if (lab >= lo && lab < hi) clsp[(size_t)lab * cs + k] = 1.0f;
            }
        }
    }
}

__device__ __forceinline__ void zero_dispatch(float* __restrict__ out, int u) {
    const int b = u / UNITS8_PER_B;
    const int r = u - b * UNITS8_PER_B;
    if      (r < 32768) zero_unit<0>(out, b, r);
    else if (r < 40960) zero_unit<1>(out, b, r - 32768);
    else if (r < 43008) zero_unit<2>(out, b, r - 40960);
    else if (r < 43520) zero_unit<3>(out, b, r - 43008);
    else                zero_unit<4>(out, b, r - 43520);
}

__device__ __forceinline__ void patch_dispatch(float* __restrict__ out, int u) {
    const int b = u / UNITS8_PER_B;
    const int r = u - b * UNITS8_PER_B;
    if      (r < 32768) patch_unit<0>(out, b, r);
    else if (r < 40960) patch_unit<1>(out, b, r - 32768);
    else if (r < 43008) patch_unit<2>(out, b, r - 40960);
    else if (r < 43520) patch_unit<3>(out, b, r - 43008);
    else                patch_unit<4>(out, b, r - 43520);
}

// ---------------- K2: PDL writer — zeros overlap prep, patches after sync -----
__global__ __launch_bounds__(WBLK)
void write_kernel(float* __restrict__ out) {
    const int u  = blockIdx.x * WBLK + threadIdx.x;
    const int u2 = u + WGRID * WBLK;

    zero_dispatch(out, u);
    if (u2 < TOTAL_UNITS) zero_dispatch(out, u2);

    cudaGridDependencySynchronize();   // wait for prep_kernel's writes

    patch_dispatch(out, u);
    if (u2 < TOTAL_UNITS) patch_dispatch(out, u2);
}

extern "C" void kernel_launch(void* const* d_in, const int* in_sizes, int n_in,
                              void* d_out, int out_size) {
    const float* boxes  = (const float*)d_in[0];
    const int*   labels = (const int*)d_in[1];
    float* out = (float*)d_out;

    dim3 pgrid(31, B_);
    prep_kernel<<<pgrid, 256>>>(boxes, labels);

    cudaLaunchConfig_t cfg = {};
    cfg.gridDim  = dim3(WGRID, 1, 1);
    cfg.blockDim = dim3(WBLK, 1, 1);
    cudaLaunchAttribute attr[1];
    attr[0].id = cudaLaunchAttributeProgrammaticStreamSerialization;
    attr[0].val.programmaticStreamSerializationAllowed = 1;
    cfg.attrs = attr;
    cfg.numAttrs = 1;
    cudaLaunchKernelEx(&cfg, write_kernel, out);
}